// round 1
// baseline (speedup 1.0000x reference)
#include <cuda_runtime.h>
#include <cstdint>

#define B_  8
#define S_  2048
#define D_  768
#define M1  (B_ * S_)

#define BM 128
#define BN 128
#define BK 16
#define TM 8
#define TN 8

// ---------------- scratch (device globals: allocation-free) ----------------
__device__ float g_Q[(size_t)M1 * D_];
__device__ float g_K[(size_t)M1 * D_];
__device__ float g_V[(size_t)M1 * D_];
__device__ float g_S[(size_t)B_ * S_ * S_];

// ---------------- JAX threefry2x32, partitionable path ----------------
// key(42) -> (k0,k1) = (0,42). Per element linear idx i (< 2^32):
// counts = (hi=0, lo=i). 20 rounds. 32-bit output = x0 ^ x1.
__device__ __forceinline__ uint32_t rotl32(uint32_t x, uint32_t d) {
    return (x << d) | (x >> (32u - d));
}

__device__ __forceinline__ float tf32_uniform(uint32_t idx) {
    const uint32_t K0 = 0u;
    const uint32_t K1 = 42u;
    const uint32_t K2 = 0x1BD11BDAu ^ 0u ^ 42u;
    uint32_t x0 = 0u  + K0;   // counts_hi + ks0
    uint32_t x1 = idx + K1;   // counts_lo + ks1
#define TF_R4(a,b,c,d) \
    x0 += x1; x1 = rotl32(x1,(a)); x1 ^= x0; \
    x0 += x1; x1 = rotl32(x1,(b)); x1 ^= x0; \
    x0 += x1; x1 = rotl32(x1,(c)); x1 ^= x0; \
    x0 += x1; x1 = rotl32(x1,(d)); x1 ^= x0;
    TF_R4(13,15,26, 6)  x0 += K1; x1 += K2 + 1u;
    TF_R4(17,29,16,24)  x0 += K2; x1 += K0 + 2u;
    TF_R4(13,15,26, 6)  x0 += K0; x1 += K1 + 3u;
    TF_R4(17,29,16,24)  x0 += K1; x1 += K2 + 4u;
    TF_R4(13,15,26, 6)  x0 += K2; x1 += K0 + 5u;
#undef TF_R4
    uint32_t bits = x0 ^ x1;
    return __uint_as_float((bits >> 9) | 0x3f800000u) - 1.0f;
}

// ---------------- shared tiled fp32 GEMM body ----------------
// A: row-major M x K. B: if BTRANS, row-major N x K (we compute A*B^T),
// else row-major K x N (ldb = row stride of B).
// All dims divide BM/BN/BK exactly for this problem -> no bounds checks.
template <bool BTRANS>
__device__ __forceinline__ void gemm_body(const float* __restrict__ A,
                                          const float* __restrict__ Bm,
                                          int K, int ldb,
                                          float (&acc)[TM][TN]) {
    __shared__ float As[BK][BM];
    __shared__ float Bs[BK][BN];
    const int tid  = threadIdx.x;
    const int row0 = blockIdx.y * BM;
    const int col0 = blockIdx.x * BN;
    const int ty = tid >> 4, tx = tid & 15;

#pragma unroll
    for (int i = 0; i < TM; ++i)
#pragma unroll
        for (int j = 0; j < TN; ++j) acc[i][j] = 0.0f;

    for (int kt = 0; kt < K; kt += BK) {
        // A tile: 128 rows x 16 k, transposed into As[k][m]
#pragma unroll
        for (int p = 0; p < 2; ++p) {
            int s  = tid + (p << 8);
            int r  = s >> 2;
            int kc = (s & 3) << 2;
            float4 va = *reinterpret_cast<const float4*>(
                A + (size_t)(row0 + r) * K + kt + kc);
            As[kc + 0][r] = va.x; As[kc + 1][r] = va.y;
            As[kc + 2][r] = va.z; As[kc + 3][r] = va.w;
        }
        if (BTRANS) {
            // B is N x K: tile 128 n-rows x 16 k, transpose into Bs[k][n]
#pragma unroll
            for (int p = 0; p < 2; ++p) {
                int s  = tid + (p << 8);
                int r  = s >> 2;
                int kc = (s & 3) << 2;
                float4 vb = *reinterpret_cast<const float4*>(
                    Bm + (size_t)(col0 + r) * ldb + kt + kc);
                Bs[kc + 0][r] = vb.x; Bs[kc + 1][r] = vb.y;
                Bs[kc + 2][r] = vb.z; Bs[kc + 3][r] = vb.w;
            }
        } else {
            // B is K x N: tile 16 k-rows x 128 n, direct float4
#pragma unroll
            for (int p = 0; p < 2; ++p) {
                int s  = tid + (p << 8);
                int kr = s >> 5;
                int nc = (s & 31) << 2;
                *reinterpret_cast<float4*>(&Bs[kr][nc]) =
                    *reinterpret_cast<const float4*>(
                        Bm + (size_t)(kt + kr) * ldb + col0 + nc);
            }
        }
        __syncthreads();
#pragma unroll
        for (int kk = 0; kk < BK; ++kk) {
            float a[TM], b[TN];
            *reinterpret_cast<float4*>(&a[0]) =
                *reinterpret_cast<const float4*>(&As[kk][ty * TM]);
            *reinterpret_cast<float4*>(&a[4]) =
                *reinterpret_cast<const float4*>(&As[kk][ty * TM + 4]);
            *reinterpret_cast<float4*>(&b[0]) =
                *reinterpret_cast<const float4*>(&Bs[kk][tx * TN]);
            *reinterpret_cast<float4*>(&b[4]) =
                *reinterpret_cast<const float4*>(&Bs[kk][tx * TN + 4]);
#pragma unroll
            for (int i = 0; i < TM; ++i)
#pragma unroll
                for (int j = 0; j < TN; ++j)
                    acc[i][j] = fmaf(a[i], b[j], acc[i][j]);
        }
        __syncthreads();
    }
}

// ---------------- kernel 1: X @ W + bias  (M1 x 768 x 768) ----------------
__global__ __launch_bounds__(256, 2)
void proj_kernel(const float* __restrict__ X, const float* __restrict__ W,
                 const float* __restrict__ bias, float* __restrict__ C) {
    float acc[TM][TN];
    gemm_body<false>(X, W, D_, D_, acc);
    const int tid  = threadIdx.x;
    const int row0 = blockIdx.y * BM, col0 = blockIdx.x * BN;
    const int ty = tid >> 4, tx = tid & 15;
#pragma unroll
    for (int i = 0; i < TM; ++i) {
        const int r = row0 + ty * TM + i;
#pragma unroll
        for (int j = 0; j < TN; j += 4) {
            const int c = col0 + tx * TN + j;
            float4 o;
            o.x = acc[i][j + 0] + bias[c + 0];
            o.y = acc[i][j + 1] + bias[c + 1];
            o.z = acc[i][j + 2] + bias[c + 2];
            o.w = acc[i][j + 3] + bias[c + 3];
            *reinterpret_cast<float4*>(C + (size_t)r * D_ + c) = o;
        }
    }
}

// ------- kernel 2: scores = (Q K^T)/sqrt(D) with pre-softmax dropout -------
__global__ __launch_bounds__(256, 2)
void scores_kernel() {
    const int bz = blockIdx.z;
    const float* A  = g_Q + (size_t)bz * S_ * D_;
    const float* Bm = g_K + (size_t)bz * S_ * D_;
    float* C = g_S + (size_t)bz * S_ * S_;
    float acc[TM][TN];
    gemm_body<true>(A, Bm, D_, D_, acc);
    const int tid  = threadIdx.x;
    const int row0 = blockIdx.y * BM, col0 = blockIdx.x * BN;
    const int ty = tid >> 4, tx = tid & 15;
    const float invscale = 0.03608439182435161f;  // 1/sqrt(768)
#pragma unroll
    for (int i = 0; i < TM; ++i) {
        const int r = row0 + ty * TM + i;
        const uint32_t ibase =
            ((uint32_t)bz * (uint32_t)S_ + (uint32_t)r) * (uint32_t)S_;
#pragma unroll
        for (int j = 0; j < TN; ++j) {
            const int c = col0 + tx * TN + j;
            const float u   = tf32_uniform(ibase + (uint32_t)c);
            const float val = acc[i][j] * invscale;
            // keep (u < 0.8): scale by 1/0.8; drop: 0 (pre-softmax!)
            C[(size_t)r * S_ + c] = (u < 0.8f) ? val * 1.25f : 0.0f;
        }
    }
}

// -------- kernel 3: softmax over k, then post-softmax mask -> 1e-9 --------
__global__ __launch_bounds__(256)
void softmax_mask_kernel(const int* __restrict__ mask) {
    const int row = blockIdx.x;  // b*S + q, 0..16383
    float* srow = g_S + (size_t)row * S_;
    const int* mrow = mask + (size_t)row * S_;
    const int t = threadIdx.x;
    __shared__ float red[8];

    float v[8];
#pragma unroll
    for (int i = 0; i < 8; ++i) v[i] = srow[t + (i << 8)];

    float mx = v[0];
#pragma unroll
    for (int i = 1; i < 8; ++i) mx = fmaxf(mx, v[i]);
#pragma unroll
    for (int o = 16; o > 0; o >>= 1)
        mx = fmaxf(mx, __shfl_xor_sync(0xffffffffu, mx, o));
    if ((t & 31) == 0) red[t >> 5] = mx;
    __syncthreads();
    if (t < 32) {
        float m2 = (t < 8) ? red[t] : -3.4e38f;
#pragma unroll
        for (int o = 4; o > 0; o >>= 1)
            m2 = fmaxf(m2, __shfl_xor_sync(0xffffffffu, m2, o));
        if (t == 0) red[0] = m2;
    }
    __syncthreads();
    mx = red[0];
    __syncthreads();

    float sum = 0.0f;
#pragma unroll
    for (int i = 0; i < 8; ++i) { v[i] = __expf(v[i] - mx); sum += v[i]; }
#pragma unroll
    for (int o = 16; o > 0; o >>= 1)
        sum += __shfl_xor_sync(0xffffffffu, sum, o);
    if ((t & 31) == 0) red[t >> 5] = sum;
    __syncthreads();
    if (t < 32) {
        float s2 = (t < 8) ? red[t] : 0.0f;
#pragma unroll
        for (int o = 4; o > 0; o >>= 1)
            s2 += __shfl_xor_sync(0xffffffffu, s2, o);
        if (t == 0) red[0] = s2;
    }
    __syncthreads();
    const float inv = 1.0f / red[0];
#pragma unroll
    for (int i = 0; i < 8; ++i) {
        const int c = t + (i << 8);
        srow[c] = (mrow[c] == 0) ? 1e-9f : v[i] * inv;
    }
}

// ---------------- kernel 4: out = att @ V  (per batch 2048x768x2048) ------
__global__ __launch_bounds__(256, 2)
void out_kernel(float* __restrict__ Og) {
    const int bz = blockIdx.z;
    const float* A  = g_S + (size_t)bz * S_ * S_;
    const float* Bm = g_V + (size_t)bz * S_ * D_;
    float* C = Og + (size_t)bz * S_ * D_;
    float acc[TM][TN];
    gemm_body<false>(A, Bm, S_, D_, acc);
    const int tid  = threadIdx.x;
    const int row0 = blockIdx.y * BM, col0 = blockIdx.x * BN;
    const int ty = tid >> 4, tx = tid & 15;
#pragma unroll
    for (int i = 0; i < TM; ++i) {
        const int r = row0 + ty * TM + i;
#pragma unroll
        for (int j = 0; j < TN; j += 4) {
            const int c = col0 + tx * TN + j;
            float4 o;
            o.x = acc[i][j + 0];
            o.y = acc[i][j + 1];
            o.z = acc[i][j + 2];
            o.w = acc[i][j + 3];
            *reinterpret_cast<float4*>(C + (size_t)r * D_ + c) = o;
        }
    }
}

// ---------------- launch ----------------
extern "C" void kernel_launch(void* const* d_in, const int* in_sizes, int n_in,
                              void* d_out, int out_size) {
    const float* q    = (const float*)d_in[0];
    const float* k    = (const float*)d_in[1];
    const float* v    = (const float*)d_in[2];
    const int*   mask = (const int*)  d_in[3];
    const float* Wq   = (const float*)d_in[4];
    const float* bq   = (const float*)d_in[5];
    const float* Wk   = (const float*)d_in[6];
    const float* bk   = (const float*)d_in[7];
    const float* Wv   = (const float*)d_in[8];
    const float* bv   = (const float*)d_in[9];

    float *Qp, *Kp, *Vp;
    cudaGetSymbolAddress((void**)&Qp, g_Q);
    cudaGetSymbolAddress((void**)&Kp, g_K);
    cudaGetSymbolAddress((void**)&Vp, g_V);

    dim3 blk(256);
    dim3 gproj(D_ / BN, M1 / BM);          // 6 x 128
    proj_kernel<<<gproj, blk>>>(q, Wq, bq, Qp);
    proj_kernel<<<gproj, blk>>>(k, Wk, bk, Kp);
    proj_kernel<<<gproj, blk>>>(v, Wv, bv, Vp);

    dim3 gsc(S_ / BN, S_ / BM, B_);        // 16 x 16 x 8
    scores_kernel<<<gsc, blk>>>();

    softmax_mask_kernel<<<M1, blk>>>(mask);

    dim3 gout(D_ / BN, S_ / BM, B_);       // 6 x 16 x 8
    out_kernel<<<gout, blk>>>((float*)d_out);
}

// round 2
// speedup vs baseline: 1.8890x; 1.8890x over previous
#include <cuda_runtime.h>
#include <cstdint>

#define B_  8
#define S_  2048
#define D_  768
#define M1  (B_ * S_)

#define BM 128
#define BN 128
#define BK 32
#define SMS 36   // smem row stride (pad: bank = 4*row+k, conflict-free fragments)

// ---------------- scratch ----------------
__device__ float g_Q[(size_t)M1 * D_];
__device__ float g_K[(size_t)M1 * D_];
__device__ float g_V[(size_t)M1 * D_];
__device__ float g_S[(size_t)B_ * S_ * S_];

// ---------------- JAX threefry2x32 (verified bit-exact in R1) ----------------
__device__ __forceinline__ uint32_t rotl32(uint32_t x, uint32_t d) {
    return (x << d) | (x >> (32u - d));
}
__device__ __forceinline__ float tf_uniform(uint32_t idx) {
    const uint32_t K0 = 0u, K1 = 42u, K2 = 0x1BD11BDAu ^ 42u;
    uint32_t x0 = 0u + K0, x1 = idx + K1;
#define TF_R4(a,b,c,d) \
    x0 += x1; x1 = rotl32(x1,(a)); x1 ^= x0; \
    x0 += x1; x1 = rotl32(x1,(b)); x1 ^= x0; \
    x0 += x1; x1 = rotl32(x1,(c)); x1 ^= x0; \
    x0 += x1; x1 = rotl32(x1,(d)); x1 ^= x0;
    TF_R4(13,15,26, 6)  x0 += K1; x1 += K2 + 1u;
    TF_R4(17,29,16,24)  x0 += K2; x1 += K0 + 2u;
    TF_R4(13,15,26, 6)  x0 += K0; x1 += K1 + 3u;
    TF_R4(17,29,16,24)  x0 += K1; x1 += K2 + 4u;
    TF_R4(13,15,26, 6)  x0 += K2; x1 += K0 + 5u;
#undef TF_R4
    uint32_t bits = x0 ^ x1;
    return __uint_as_float((bits >> 9) | 0x3f800000u) - 1.0f;
}

// ---------------- tf32 helpers ----------------
__device__ __forceinline__ uint32_t f2tf(float f) {
    uint32_t r;
    asm("cvt.rna.tf32.f32 %0, %1;" : "=r"(r) : "f"(f));
    return r;
}
__device__ __forceinline__ void mma_tf32(float (&c)[4], const uint32_t (&a)[4],
                                         const uint32_t (&b)[2]) {
    asm volatile(
        "mma.sync.aligned.m16n8k8.row.col.f32.tf32.tf32.f32 "
        "{%0,%1,%2,%3}, {%4,%5,%6,%7}, {%8,%9}, {%0,%1,%2,%3};"
        : "+f"(c[0]), "+f"(c[1]), "+f"(c[2]), "+f"(c[3])
        : "r"(a[0]), "r"(a[1]), "r"(a[2]), "r"(a[3]), "r"(b[0]), "r"(b[1]));
}

// ---------------- tf32 MMA GEMM body ----------------
// A row-major M x K (lda=K). B: BTRANS ? row-major N x K : row-major K x N (ldb).
// Block 128x128, 8 warps (2x4), warp tile 64x32. acc[mi][ni][4].
template <bool BTRANS>
__device__ __forceinline__ void gemm_mma(const float* __restrict__ A,
                                         const float* __restrict__ Bm,
                                         int K, int ldb,
                                         float (&acc)[4][4][4]) {
    __shared__ uint32_t As[BM][SMS];
    __shared__ uint32_t Bs[BN][SMS];
    const int tid  = threadIdx.x;
    const int row0 = blockIdx.y * BM;
    const int col0 = blockIdx.x * BN;
    const int lane = tid & 31, warp = tid >> 5;
    const int wm = (warp & 1) * 64;       // warp M offset
    const int wn = (warp >> 1) * 32;      // warp N offset
    const int g = lane >> 2, t = lane & 3;

#pragma unroll
    for (int mi = 0; mi < 4; ++mi)
#pragma unroll
        for (int ni = 0; ni < 4; ++ni)
#pragma unroll
            for (int q = 0; q < 4; ++q) acc[mi][ni][q] = 0.0f;

    const int ar = tid >> 3;              // 0..31
    const int ak = (tid & 7) << 2;        // 0,4,..,28
    const int bkr = tid >> 5;             // 0..7
    const int bnc = (tid & 31) << 2;      // 0..124

    for (int kt = 0; kt < K; kt += BK) {
        // A tile 128x32
#pragma unroll
        for (int p = 0; p < 4; ++p) {
            const int r = ar + (p << 5);
            float4 v = *reinterpret_cast<const float4*>(
                A + (size_t)(row0 + r) * K + kt + ak);
            As[r][ak + 0] = f2tf(v.x); As[r][ak + 1] = f2tf(v.y);
            As[r][ak + 2] = f2tf(v.z); As[r][ak + 3] = f2tf(v.w);
        }
        if (BTRANS) {
            // B is N x K (k contiguous) -> Bs[n][k]
#pragma unroll
            for (int p = 0; p < 4; ++p) {
                const int r = ar + (p << 5);
                float4 v = *reinterpret_cast<const float4*>(
                    Bm + (size_t)(col0 + r) * ldb + kt + ak);
                Bs[r][ak + 0] = f2tf(v.x); Bs[r][ak + 1] = f2tf(v.y);
                Bs[r][ak + 2] = f2tf(v.z); Bs[r][ak + 3] = f2tf(v.w);
            }
        } else {
            // B is K x N (n contiguous) -> transpose into Bs[n][k]
#pragma unroll
            for (int p = 0; p < 4; ++p) {
                const int kr = bkr + (p << 3);
                float4 v = *reinterpret_cast<const float4*>(
                    Bm + (size_t)(kt + kr) * ldb + col0 + bnc);
                Bs[bnc + 0][kr] = f2tf(v.x); Bs[bnc + 1][kr] = f2tf(v.y);
                Bs[bnc + 2][kr] = f2tf(v.z); Bs[bnc + 3][kr] = f2tf(v.w);
            }
        }
        __syncthreads();

#pragma unroll
        for (int ks = 0; ks < BK / 8; ++ks) {
            const int k = ks << 3;
            uint32_t a[4][4];
#pragma unroll
            for (int mi = 0; mi < 4; ++mi) {
                const int m = wm + (mi << 4);
                a[mi][0] = As[m + g    ][k + t    ];
                a[mi][1] = As[m + g + 8][k + t    ];
                a[mi][2] = As[m + g    ][k + t + 4];
                a[mi][3] = As[m + g + 8][k + t + 4];
            }
            uint32_t b[4][2];
#pragma unroll
            for (int ni = 0; ni < 4; ++ni) {
                const int n = wn + (ni << 3);
                b[ni][0] = Bs[n + g][k + t    ];
                b[ni][1] = Bs[n + g][k + t + 4];
            }
#pragma unroll
            for (int mi = 0; mi < 4; ++mi)
#pragma unroll
                for (int ni = 0; ni < 4; ++ni)
                    mma_tf32(acc[mi][ni], a[mi], b[ni]);
        }
        __syncthreads();
    }
}

// ---------------- kernel 1: fused Q/K/V projections ----------------
struct ProjArgs {
    const float* X[3];
    const float* W[3];
    const float* b[3];
    float*       C[3];
};

__global__ __launch_bounds__(256, 2)
void proj_kernel(ProjArgs pa) {
    const int z = blockIdx.z;
    float acc[4][4][4];
    gemm_mma<false>(pa.X[z], pa.W[z], D_, D_, acc);

    const float* bias = pa.b[z];
    float* C = pa.C[z];
    const int tid = threadIdx.x, lane = tid & 31, warp = tid >> 5;
    const int row0 = blockIdx.y * BM + (warp & 1) * 64 + (lane >> 2);
    const int col0 = blockIdx.x * BN + (warp >> 1) * 32 + (lane & 3) * 2;
#pragma unroll
    for (int mi = 0; mi < 4; ++mi) {
#pragma unroll
        for (int ni = 0; ni < 4; ++ni) {
            const int c = col0 + (ni << 3);
            const float bx = bias[c], by = bias[c + 1];
            const int r1 = row0 + (mi << 4);
            float2 o0 = make_float2(acc[mi][ni][0] + bx, acc[mi][ni][1] + by);
            float2 o1 = make_float2(acc[mi][ni][2] + bx, acc[mi][ni][3] + by);
            *reinterpret_cast<float2*>(C + (size_t)r1 * D_ + c)       = o0;
            *reinterpret_cast<float2*>(C + (size_t)(r1 + 8) * D_ + c) = o1;
        }
    }
}

// ------- kernel 2: scores = (Q K^T)/sqrt(D) + pre-softmax dropout -------
__global__ __launch_bounds__(256, 2)
void scores_kernel() {
    const int bz = blockIdx.z;
    const float* A  = g_Q + (size_t)bz * S_ * D_;
    const float* Bm = g_K + (size_t)bz * S_ * D_;
    float* C = g_S + (size_t)bz * S_ * S_;
    float acc[4][4][4];
    gemm_mma<true>(A, Bm, D_, D_, acc);

    const int tid = threadIdx.x, lane = tid & 31, warp = tid >> 5;
    const int row0 = blockIdx.y * BM + (warp & 1) * 64 + (lane >> 2);
    const int col0 = blockIdx.x * BN + (warp >> 1) * 32 + (lane & 3) * 2;
    const float sc = 0.03608439182435161f;  // 1/sqrt(768)
#pragma unroll
    for (int mi = 0; mi < 4; ++mi) {
#pragma unroll
        for (int rr = 0; rr < 2; ++rr) {
            const int r = row0 + (mi << 4) + (rr << 3);
            const uint32_t ib = ((uint32_t)bz * S_ + (uint32_t)r) * (uint32_t)S_;
#pragma unroll
            for (int ni = 0; ni < 4; ++ni) {
                const int c = col0 + (ni << 3);
                const float v0 = acc[mi][ni][rr * 2 + 0] * sc;
                const float v1 = acc[mi][ni][rr * 2 + 1] * sc;
                const float u0 = tf_uniform(ib + (uint32_t)c);
                const float u1 = tf_uniform(ib + (uint32_t)c + 1u);
                float2 o;
                o.x = (u0 < 0.8f) ? v0 * 1.25f : 0.0f;
                o.y = (u1 < 0.8f) ? v1 * 1.25f : 0.0f;
                *reinterpret_cast<float2*>(C + (size_t)r * S_ + c) = o;
            }
        }
    }
}

// -------- kernel 3: softmax over k, then post-softmax mask -> 1e-9 --------
__global__ __launch_bounds__(256)
void softmax_mask_kernel(const int* __restrict__ mask) {
    const int row = blockIdx.x;
    float* srow = g_S + (size_t)row * S_;
    const int* mrow = mask + (size_t)row * S_;
    const int t = threadIdx.x;
    __shared__ float red[8];

    float v[8];
#pragma unroll
    for (int i = 0; i < 8; ++i) v[i] = srow[t + (i << 8)];

    float mx = v[0];
#pragma unroll
    for (int i = 1; i < 8; ++i) mx = fmaxf(mx, v[i]);
#pragma unroll
    for (int o = 16; o > 0; o >>= 1)
        mx = fmaxf(mx, __shfl_xor_sync(0xffffffffu, mx, o));
    if ((t & 31) == 0) red[t >> 5] = mx;
    __syncthreads();
    if (t < 32) {
        float m2 = (t < 8) ? red[t] : -3.4e38f;
#pragma unroll
        for (int o = 4; o > 0; o >>= 1)
            m2 = fmaxf(m2, __shfl_xor_sync(0xffffffffu, m2, o));
        if (t == 0) red[0] = m2;
    }
    __syncthreads();
    mx = red[0];
    __syncthreads();

    float sum = 0.0f;
#pragma unroll
    for (int i = 0; i < 8; ++i) { v[i] = __expf(v[i] - mx); sum += v[i]; }
#pragma unroll
    for (int o = 16; o > 0; o >>= 1)
        sum += __shfl_xor_sync(0xffffffffu, sum, o);
    if ((t & 31) == 0) red[t >> 5] = sum;
    __syncthreads();
    if (t < 32) {
        float s2 = (t < 8) ? red[t] : 0.0f;
#pragma unroll
        for (int o = 4; o > 0; o >>= 1)
            s2 += __shfl_xor_sync(0xffffffffu, s2, o);
        if (t == 0) red[0] = s2;
    }
    __syncthreads();
    const float inv = 1.0f / red[0];
#pragma unroll
    for (int i = 0; i < 8; ++i) {
        const int c = t + (i << 8);
        srow[c] = (mrow[c] == 0) ? 1e-9f : v[i] * inv;
    }
}

// ---------------- kernel 4: out = att @ V ----------------
__global__ __launch_bounds__(256, 2)
void out_kernel(float* __restrict__ Og) {
    const int bz = blockIdx.z;
    const float* A  = g_S + (size_t)bz * S_ * S_;
    const float* Bm = g_V + (size_t)bz * S_ * D_;
    float* C = Og + (size_t)bz * S_ * D_;
    float acc[4][4][4];
    gemm_mma<false>(A, Bm, S_, D_, acc);

    const int tid = threadIdx.x, lane = tid & 31, warp = tid >> 5;
    const int row0 = blockIdx.y * BM + (warp & 1) * 64 + (lane >> 2);
    const int col0 = blockIdx.x * BN + (warp >> 1) * 32 + (lane & 3) * 2;
#pragma unroll
    for (int mi = 0; mi < 4; ++mi) {
#pragma unroll
        for (int ni = 0; ni < 4; ++ni) {
            const int c = col0 + (ni << 3);
            const int r1 = row0 + (mi << 4);
            float2 o0 = make_float2(acc[mi][ni][0], acc[mi][ni][1]);
            float2 o1 = make_float2(acc[mi][ni][2], acc[mi][ni][3]);
            *reinterpret_cast<float2*>(C + (size_t)r1 * D_ + c)       = o0;
            *reinterpret_cast<float2*>(C + (size_t)(r1 + 8) * D_ + c) = o1;
        }
    }
}

// ---------------- launch ----------------
extern "C" void kernel_launch(void* const* d_in, const int* in_sizes, int n_in,
                              void* d_out, int out_size) {
    const float* q    = (const float*)d_in[0];
    const float* k    = (const float*)d_in[1];
    const float* v    = (const float*)d_in[2];
    const int*   mask = (const int*)  d_in[3];

    float *Qp, *Kp, *Vp;
    cudaGetSymbolAddress((void**)&Qp, g_Q);
    cudaGetSymbolAddress((void**)&Kp, g_K);
    cudaGetSymbolAddress((void**)&Vp, g_V);

    ProjArgs pa;
    pa.X[0] = q; pa.X[1] = k; pa.X[2] = v;
    pa.W[0] = (const float*)d_in[4]; pa.b[0] = (const float*)d_in[5];
    pa.W[1] = (const float*)d_in[6]; pa.b[1] = (const float*)d_in[7];
    pa.W[2] = (const float*)d_in[8]; pa.b[2] = (const float*)d_in[9];
    pa.C[0] = Qp; pa.C[1] = Kp; pa.C[2] = Vp;

    dim3 blk(256);
    dim3 gproj(D_ / BN, M1 / BM, 3);       // 6 x 128 x 3
    proj_kernel<<<gproj, blk>>>(pa);

    dim3 gsc(S_ / BN, S_ / BM, B_);        // 16 x 16 x 8
    scores_kernel<<<gsc, blk>>>();

    softmax_mask_kernel<<<M1, blk>>>(mask);

    dim3 gout(D_ / BN, S_ / BM, B_);       // 6 x 16 x 8
    out_kernel<<<gout, blk>>>((float*)d_out);
}

// round 3
// speedup vs baseline: 2.9540x; 1.5638x over previous
#include <cuda_runtime.h>
#include <cstdint>

#define B_  8
#define S_  2048
#define D_  768
#define M1  (B_ * S_)

#define BM 128
#define BN 128
#define BK 16
#define STAGES 4
#define ASTRIDE 20          // [m][k] pad: banks 4g+t conflict-free
#define BSTRIDE_T 20        // BTRANS: [n][k]
#define BSTRIDE_N 136       // !BTRANS: [k][n] pad: banks 8t+g conflict-free
#define ASZ (BM * ASTRIDE)          // 2560 floats
#define BSZ_T (BN * BSTRIDE_T)      // 2560
#define BSZ_N (BK * BSTRIDE_N)      // 2176

// ---------------- scratch ----------------
__device__ float g_Q[(size_t)M1 * D_];
__device__ float g_K[(size_t)M1 * D_];
__device__ float g_V[(size_t)M1 * D_];
__device__ float g_S[(size_t)B_ * S_ * S_];

// ---------------- JAX threefry2x32 (bit-exact, verified R1) ----------------
__device__ __forceinline__ uint32_t rotl32(uint32_t x, uint32_t d) {
    return (x << d) | (x >> (32u - d));
}
__device__ __forceinline__ float tf_uniform(uint32_t idx) {
    const uint32_t K0 = 0u, K1 = 42u, K2 = 0x1BD11BDAu ^ 42u;
    uint32_t x0 = 0u + K0, x1 = idx + K1;
#define TF_R4(a,b,c,d) \
    x0 += x1; x1 = rotl32(x1,(a)); x1 ^= x0; \
    x0 += x1; x1 = rotl32(x1,(b)); x1 ^= x0; \
    x0 += x1; x1 = rotl32(x1,(c)); x1 ^= x0; \
    x0 += x1; x1 = rotl32(x1,(d)); x1 ^= x0;
    TF_R4(13,15,26, 6)  x0 += K1; x1 += K2 + 1u;
    TF_R4(17,29,16,24)  x0 += K2; x1 += K0 + 2u;
    TF_R4(13,15,26, 6)  x0 += K0; x1 += K1 + 3u;
    TF_R4(17,29,16,24)  x0 += K1; x1 += K2 + 4u;
    TF_R4(13,15,26, 6)  x0 += K2; x1 += K0 + 5u;
#undef TF_R4
    uint32_t bits = x0 ^ x1;
    return __uint_as_float((bits >> 9) | 0x3f800000u) - 1.0f;
}

// ---------------- tf32 / cp.async helpers ----------------
__device__ __forceinline__ uint32_t f2tf(float f) {
    uint32_t r;
    asm("cvt.rna.tf32.f32 %0, %1;" : "=r"(r) : "f"(f));
    return r;
}
__device__ __forceinline__ void mma_tf32(float (&c)[4], const uint32_t (&a)[4],
                                         const uint32_t (&b)[2]) {
    asm volatile(
        "mma.sync.aligned.m16n8k8.row.col.f32.tf32.tf32.f32 "
        "{%0,%1,%2,%3}, {%4,%5,%6,%7}, {%8,%9}, {%0,%1,%2,%3};"
        : "+f"(c[0]), "+f"(c[1]), "+f"(c[2]), "+f"(c[3])
        : "r"(a[0]), "r"(a[1]), "r"(a[2]), "r"(a[3]), "r"(b[0]), "r"(b[1]));
}
__device__ __forceinline__ void cpa16(uint32_t sa, const void* g) {
    asm volatile("cp.async.cg.shared.global [%0], [%1], 16;" :: "r"(sa), "l"(g));
}
__device__ __forceinline__ void cpa_commit() {
    asm volatile("cp.async.commit_group;");
}
template <int N>
__device__ __forceinline__ void cpa_wait() {
    asm volatile("cp.async.wait_group %0;" :: "n"(N));
}

// ---------------- pipelined tf32 MMA GEMM body ----------------
// A row-major M x K. B: BTRANS ? row-major N x K : row-major K x N (ldb).
// Block 128x128, 8 warps (2x4), warp tile 64x32.
template <bool BTRANS>
__device__ __forceinline__ void gemm_mma(const float* __restrict__ A,
                                         const float* __restrict__ Bm,
                                         int K, int ldb,
                                         float (&acc)[4][4][4]) {
    extern __shared__ float sm[];
    const int SS = ASZ + (BTRANS ? BSZ_T : BSZ_N);  // floats per stage
    const uint32_t sbase = (uint32_t)__cvta_generic_to_shared(sm);

    const int tid  = threadIdx.x;
    const int row0 = blockIdx.y * BM;
    const int col0 = blockIdx.x * BN;
    const int lane = tid & 31, warp = tid >> 5;
    const int wm = (warp & 1) * 64;
    const int wn = (warp >> 1) * 32;
    const int g = lane >> 2, t = lane & 3;

#pragma unroll
    for (int mi = 0; mi < 4; ++mi)
#pragma unroll
        for (int ni = 0; ni < 4; ++ni)
#pragma unroll
            for (int q = 0; q < 4; ++q) acc[mi][ni][q] = 0.0f;

    // ---- async stage loader ----
    auto load_stage = [&](int s, int it) {
        const int k0 = it * BK;
        const uint32_t st = sbase + (uint32_t)(s * SS) * 4u;
#pragma unroll
        for (int p = 0; p < 2; ++p) {
            const int c  = tid + (p << 8);
            const int r  = c >> 2;
            const int kc = (c & 3) << 2;
            cpa16(st + (uint32_t)(r * ASTRIDE + kc) * 4u,
                  A + (size_t)(row0 + r) * K + k0 + kc);
        }
        if (BTRANS) {
#pragma unroll
            for (int p = 0; p < 2; ++p) {
                const int c  = tid + (p << 8);
                const int r  = c >> 2;
                const int kc = (c & 3) << 2;
                cpa16(st + (uint32_t)(ASZ + r * BSTRIDE_T + kc) * 4u,
                      Bm + (size_t)(col0 + r) * ldb + k0 + kc);
            }
        } else {
#pragma unroll
            for (int p = 0; p < 2; ++p) {
                const int c  = tid + (p << 8);
                const int kr = c >> 5;
                const int nc = (c & 31) << 2;
                cpa16(st + (uint32_t)(ASZ + kr * BSTRIDE_N + nc) * 4u,
                      Bm + (size_t)(k0 + kr) * ldb + col0 + nc);
            }
        }
    };

    const int nk = K / BK;

    // prologue: prefetch STAGES-1 stages
#pragma unroll
    for (int p = 0; p < STAGES - 1; ++p) {
        load_stage(p, p);
        cpa_commit();
    }

    for (int i = 0; i < nk; ++i) {
        cpa_wait<STAGES - 2>();
        __syncthreads();

        const int ld = i + STAGES - 1;
        if (ld < nk) load_stage(ld & (STAGES - 1), ld);
        cpa_commit();

        const float* As = sm + (i & (STAGES - 1)) * SS;
        const float* Bs = As + ASZ;
#pragma unroll
        for (int ks = 0; ks < BK / 8; ++ks) {
            const int k = ks << 3;
            uint32_t a[4][4];
#pragma unroll
            for (int mi = 0; mi < 4; ++mi) {
                const int m = wm + (mi << 4);
                a[mi][0] = f2tf(As[(m + g    ) * ASTRIDE + k + t    ]);
                a[mi][1] = f2tf(As[(m + g + 8) * ASTRIDE + k + t    ]);
                a[mi][2] = f2tf(As[(m + g    ) * ASTRIDE + k + t + 4]);
                a[mi][3] = f2tf(As[(m + g + 8) * ASTRIDE + k + t + 4]);
            }
            uint32_t b[4][2];
#pragma unroll
            for (int ni = 0; ni < 4; ++ni) {
                const int n = wn + (ni << 3);
                if (BTRANS) {
                    b[ni][0] = f2tf(Bs[(n + g) * BSTRIDE_T + k + t    ]);
                    b[ni][1] = f2tf(Bs[(n + g) * BSTRIDE_T + k + t + 4]);
                } else {
                    b[ni][0] = f2tf(Bs[(k + t    ) * BSTRIDE_N + n + g]);
                    b[ni][1] = f2tf(Bs[(k + t + 4) * BSTRIDE_N + n + g]);
                }
            }
#pragma unroll
            for (int mi = 0; mi < 4; ++mi)
#pragma unroll
                for (int ni = 0; ni < 4; ++ni)
                    mma_tf32(acc[mi][ni], a[mi], b[ni]);
        }
    }
    cpa_wait<0>();
}

// ---------------- kernel 1: fused Q/K/V projections ----------------
struct ProjArgs {
    const float* X[3];
    const float* W[3];
    const float* b[3];
    float*       C[3];
};

__global__ __launch_bounds__(256, 2)
void proj_kernel(ProjArgs pa) {
    const int z = blockIdx.z;
    float acc[4][4][4];
    gemm_mma<false>(pa.X[z], pa.W[z], D_, D_, acc);

    const float* bias = pa.b[z];
    float* C = pa.C[z];
    const int tid = threadIdx.x, lane = tid & 31, warp = tid >> 5;
    const int row0 = blockIdx.y * BM + (warp & 1) * 64 + (lane >> 2);
    const int col0 = blockIdx.x * BN + (warp >> 1) * 32 + (lane & 3) * 2;
#pragma unroll
    for (int mi = 0; mi < 4; ++mi) {
#pragma unroll
        for (int ni = 0; ni < 4; ++ni) {
            const int c = col0 + (ni << 3);
            const float bx = __ldg(bias + c), by = __ldg(bias + c + 1);
            const int r1 = row0 + (mi << 4);
            float2 o0 = make_float2(acc[mi][ni][0] + bx, acc[mi][ni][1] + by);
            float2 o1 = make_float2(acc[mi][ni][2] + bx, acc[mi][ni][3] + by);
            *reinterpret_cast<float2*>(C + (size_t)r1 * D_ + c)       = o0;
            *reinterpret_cast<float2*>(C + (size_t)(r1 + 8) * D_ + c) = o1;
        }
    }
}

// ------- kernel 2: scores = (Q K^T)/sqrt(D) + pre-softmax dropout -------
__global__ __launch_bounds__(256, 2)
void scores_kernel() {
    const int bz = blockIdx.z;
    const float* A  = g_Q + (size_t)bz * S_ * D_;
    const float* Bm = g_K + (size_t)bz * S_ * D_;
    float* C = g_S + (size_t)bz * S_ * S_;
    float acc[4][4][4];
    gemm_mma<true>(A, Bm, D_, D_, acc);

    const int tid = threadIdx.x, lane = tid & 31, warp = tid >> 5;
    const int row0 = blockIdx.y * BM + (warp & 1) * 64 + (lane >> 2);
    const int col0 = blockIdx.x * BN + (warp >> 1) * 32 + (lane & 3) * 2;
    const float sc = 0.03608439182435161f;  // 1/sqrt(768)
#pragma unroll
    for (int mi = 0; mi < 4; ++mi) {
#pragma unroll
        for (int rr = 0; rr < 2; ++rr) {
            const int r = row0 + (mi << 4) + (rr << 3);
            const uint32_t ib = ((uint32_t)bz * S_ + (uint32_t)r) * (uint32_t)S_;
#pragma unroll
            for (int ni = 0; ni < 4; ++ni) {
                const int c = col0 + (ni << 3);
                const float v0 = acc[mi][ni][rr * 2 + 0] * sc;
                const float v1 = acc[mi][ni][rr * 2 + 1] * sc;
                const float u0 = tf_uniform(ib + (uint32_t)c);
                const float u1 = tf_uniform(ib + (uint32_t)c + 1u);
                float2 o;
                o.x = (u0 < 0.8f) ? v0 * 1.25f : 0.0f;
                o.y = (u1 < 0.8f) ? v1 * 1.25f : 0.0f;
                *reinterpret_cast<float2*>(C + (size_t)r * S_ + c) = o;
            }
        }
    }
}

// -------- kernel 3: softmax over k, then post-softmax mask -> 1e-9 --------
__global__ __launch_bounds__(256)
void softmax_mask_kernel(const int* __restrict__ mask) {
    const int row = blockIdx.x;
    float* srow = g_S + (size_t)row * S_;
    const int* mrow = mask + (size_t)row * S_;
    const int t = threadIdx.x;
    __shared__ float red[8];

    float v[8];
#pragma unroll
    for (int i = 0; i < 8; ++i) v[i] = srow[t + (i << 8)];

    float mx = v[0];
#pragma unroll
    for (int i = 1; i < 8; ++i) mx = fmaxf(mx, v[i]);
#pragma unroll
    for (int o = 16; o > 0; o >>= 1)
        mx = fmaxf(mx, __shfl_xor_sync(0xffffffffu, mx, o));
    if ((t & 31) == 0) red[t >> 5] = mx;
    __syncthreads();
    if (t < 32) {
        float m2 = (t < 8) ? red[t] : -3.4e38f;
#pragma unroll
        for (int o = 4; o > 0; o >>= 1)
            m2 = fmaxf(m2, __shfl_xor_sync(0xffffffffu, m2, o));
        if (t == 0) red[0] = m2;
    }
    __syncthreads();
    mx = red[0];
    __syncthreads();

    float sum = 0.0f;
#pragma unroll
    for (int i = 0; i < 8; ++i) { v[i] = __expf(v[i] - mx); sum += v[i]; }
#pragma unroll
    for (int o = 16; o > 0; o >>= 1)
        sum += __shfl_xor_sync(0xffffffffu, sum, o);
    if ((t & 31) == 0) red[t >> 5] = sum;
    __syncthreads();
    if (t < 32) {
        float s2 = (t < 8) ? red[t] : 0.0f;
#pragma unroll
        for (int o = 4; o > 0; o >>= 1)
            s2 += __shfl_xor_sync(0xffffffffu, s2, o);
        if (t == 0) red[0] = s2;
    }
    __syncthreads();
    const float inv = 1.0f / red[0];
#pragma unroll
    for (int i = 0; i < 8; ++i) {
        const int c = t + (i << 8);
        srow[c] = (mrow[c] == 0) ? 1e-9f : v[i] * inv;
    }
}

// ---------------- kernel 4: out = att @ V ----------------
__global__ __launch_bounds__(256, 2)
void out_kernel(float* __restrict__ Og) {
    const int bz = blockIdx.z;
    const float* A  = g_S + (size_t)bz * S_ * S_;
    const float* Bm = g_V + (size_t)bz * S_ * D_;
    float* C = Og + (size_t)bz * S_ * D_;
    float acc[4][4][4];
    gemm_mma<false>(A, Bm, S_, D_, acc);

    const int tid = threadIdx.x, lane = tid & 31, warp = tid >> 5;
    const int row0 = blockIdx.y * BM + (warp & 1) * 64 + (lane >> 2);
    const int col0 = blockIdx.x * BN + (warp >> 1) * 32 + (lane & 3) * 2;
#pragma unroll
    for (int mi = 0; mi < 4; ++mi) {
#pragma unroll
        for (int ni = 0; ni < 4; ++ni) {
            const int c = col0 + (ni << 3);
            const int r1 = row0 + (mi << 4);
            float2 o0 = make_float2(acc[mi][ni][0], acc[mi][ni][1]);
            float2 o1 = make_float2(acc[mi][ni][2], acc[mi][ni][3]);
            *reinterpret_cast<float2*>(C + (size_t)r1 * D_ + c)       = o0;
            *reinterpret_cast<float2*>(C + (size_t)(r1 + 8) * D_ + c) = o1;
        }
    }
}

// ---------------- launch ----------------
extern "C" void kernel_launch(void* const* d_in, const int* in_sizes, int n_in,
                              void* d_out, int out_size) {
    const float* q    = (const float*)d_in[0];
    const float* k    = (const float*)d_in[1];
    const float* v    = (const float*)d_in[2];
    const int*   mask = (const int*)  d_in[3];

    float *Qp, *Kp, *Vp;
    cudaGetSymbolAddress((void**)&Qp, g_Q);
    cudaGetSymbolAddress((void**)&Kp, g_K);
    cudaGetSymbolAddress((void**)&Vp, g_V);

    ProjArgs pa;
    pa.X[0] = q; pa.X[1] = k; pa.X[2] = v;
    pa.W[0] = (const float*)d_in[4]; pa.b[0] = (const float*)d_in[5];
    pa.W[1] = (const float*)d_in[6]; pa.b[1] = (const float*)d_in[7];
    pa.W[2] = (const float*)d_in[8]; pa.b[2] = (const float*)d_in[9];
    pa.C[0] = Qp; pa.C[1] = Kp; pa.C[2] = Vp;

    const int smem_n = (ASZ + BSZ_N) * 4 * STAGES;  // 75776 B
    const int smem_t = (ASZ + BSZ_T) * 4 * STAGES;  // 81920 B
    cudaFuncSetAttribute(proj_kernel,
        cudaFuncAttributeMaxDynamicSharedMemorySize, smem_n);
    cudaFuncSetAttribute(scores_kernel,
        cudaFuncAttributeMaxDynamicSharedMemorySize, smem_t);
    cudaFuncSetAttribute(out_kernel,
        cudaFuncAttributeMaxDynamicSharedMemorySize, smem_n);

    dim3 blk(256);
    dim3 gproj(D_ / BN, M1 / BM, 3);
    proj_kernel<<<gproj, blk, smem_n>>>(pa);

    dim3 gsc(S_ / BN, S_ / BM, B_);
    scores_kernel<<<gsc, blk, smem_t>>>();

    softmax_mask_kernel<<<M1, blk>>>(mask);

    dim3 gout(D_ / BN, S_ / BM, B_);
    out_kernel<<<gout, blk, smem_n>>>((float*)d_out);
}